// round 12
// baseline (speedup 1.0000x reference)
#include <cuda_runtime.h>
#include <math.h>

#define B_  32
#define NH  778
#define NO  3000
#define Z_  64
#define NPRIOR 204

#define NT_PAD      800
#define FUS_SEGS    8
#define FUS_SEGLEN  100
#define FUS_CHUNKS  6          // 6*512 = 3072 >= 3000 (2 queries/thread)
#define FUS_ITEMS   (FUS_SEGS * FUS_CHUNKS * B_)    // 1536
#define PRIOR_PAD   208
#define PRIOR_ITEMS (FUS_CHUNKS * B_)               // 192 (first: longest blocks)
#define TOTAL_ITEMS (FUS_ITEMS + PRIOR_ITEMS)       // 1728

#define MSE_ITEMS   ((B_ * NH * 3) / 4)             // 18672 float4
#define MSE_PER_BLK 98                              // 98*192 >= 18672
#define KLD_PER_BLK 11                              // 11*192 >= 2048

// Merged via atomicMax(~bits): zero = identity; consumers reset to 0 for replay.
__device__ unsigned g_okr[B_ * NO];
__device__ unsigned g_okg[B_ * NO];
__device__ float    g_mp[B_ * NO];
__device__ unsigned g_cmr[B_ * NT_PAD];
__device__ unsigned g_cmg[B_ * NT_PAD];
// acc: 0 penetr, 1 npts, 2 contact, 3 consist, 4 loss_o, 5 loss_h, 6 mse, 7 kld
__device__ double   g_acc[8];
__device__ unsigned g_done_chunk[B_ * FUS_CHUNKS];  // -> 9
__device__ unsigned g_done_batch[B_];               // -> 48
__device__ unsigned g_done_all;                     // -> 1728

__constant__ int c_prior[NPRIOR] = {
  697,698,699,700,712,713,714,715,737,738,739,740,741,743,744,745,
  746,748,749,750,753,754,755,756,757,758,759,760,761,762,763,764,
  765,766,767,768,
  46,47,48,49,164,165,166,167,194,195,223,237,238,280,281,298,
  301,317,320,323,324,325,326,327,328,329,330,331,332,333,340,341,
  342,343,344,345,346,347,348,349,350,351,352,353,354,355,
  356,357,358,359,375,376,386,387,396,397,402,403,413,429,433,434,
  435,436,437,438,439,440,441,442,443,444,452,453,454,455,456,459,
  460,461,462,463,464,465,466,467,
  468,469,470,471,484,485,486,496,497,506,507,513,514,524,545,546,
  547,548,549,550,551,552,553,555,563,564,565,566,567,570,572,573,
  574,575,576,577,578,
  580,581,582,583,600,601,602,614,615,624,625,630,631,641,663,664,
  665,666,667,668,670,672,680,681,682,683,684,686,687,688,689,690,
  691,692,693,694,695,
  73,96,98,99,772,774,775,777
};

typedef unsigned long long u64;

__device__ __forceinline__ u64 fma2(u64 a, u64 b, u64 c) {
    u64 d;
    asm("fma.rn.f32x2 %0, %1, %2, %3;" : "=l"(d) : "l"(a), "l"(b), "l"(c));
    return d;
}
__device__ __forceinline__ u64 add2(u64 a, u64 b) {
    u64 d;
    asm("add.rn.f32x2 %0, %1, %2;" : "=l"(d) : "l"(a), "l"(b));
    return d;
}
__device__ __forceinline__ u64 pack2(float lo, float hi) {
    u64 d;
    asm("mov.b64 %0, {%1, %2};" : "=l"(d) : "r"(__float_as_uint(lo)), "r"(__float_as_uint(hi)));
    return d;
}
__device__ __forceinline__ void unpack2u(u64 v, unsigned& lo, unsigned& hi) {
    asm("mov.b64 {%0, %1}, %2;" : "=r"(lo), "=r"(hi) : "l"(v));
}
__device__ __forceinline__ float warp_sum(float v) {
#pragma unroll
    for (int o = 16; o > 0; o >>= 1) v += __shfl_down_sync(0xffffffffu, v, o);
    return v;
}
__device__ __forceinline__ float sgnf(float x) {
    return (x > 0.f) ? 1.f : ((x < 0.f) ? -1.f : 0.f);
}

// block-reduce n<=5 floats (uses caller's smem), then one atomicAdd(double) each
__device__ __forceinline__ void block_acc(float* vals, int n, int accbase,
                                          float (*red)[8], int tid) {
    const int lane = tid & 31, warp = tid >> 5;
    for (int q = 0; q < n; q++) {
        float v = warp_sum(vals[q]);
        if (lane == 0) red[warp][q] = v;
    }
    __syncthreads();
    if (tid < n) {
        float s = 0.f;
#pragma unroll
        for (int wi = 0; wi < 8; wi++) s += red[wi][tid];
        atomicAdd(&g_acc[accbase + tid], (double)s);
    }
    __syncthreads();
}

__device__ void obj_epilogue(int b, int chunk,
    const float* __restrict__ recon, const float* __restrict__ gt,
    const float* __restrict__ recon_n, const float* __restrict__ gt_n,
    const float* __restrict__ obj, float (*red)[8], int tid)
{
    float a[5] = {0.f,0.f,0.f,0.f,0.f};
    const float* rb  = recon   + (size_t)b * NH * 3;
    const float* gb  = gt      + (size_t)b * NH * 3;
    const float* rnb = recon_n + (size_t)b * NH * 3;
    const float* gnb = gt_n    + (size_t)b * NH * 3;
    const float* ob  = obj     + (size_t)b * NO * 3;
#pragma unroll
    for (int it = 0; it < 2; it++) {
        const int j = chunk * 512 + it * 256 + tid;
        if (j >= NO) continue;
        const int idx = b * NO + j;
        const unsigned br = ~g_okr[idx];
        const unsigned bg = ~g_okg[idx];
        const float mp = g_mp[idx];
        g_okr[idx] = 0u;
        g_okg[idx] = 0u;

        const float ox = ob[3*j], oy = ob[3*j+1], oz = ob[3*j+2];
        const int ir = (int)(br & 1023u);
        const int ig = (int)(bg & 1023u);

        float dxr = ox - rb[3*ir], dyr = oy - rb[3*ir+1], dzr = oz - rb[3*ir+2];
        float d2r = dxr*dxr + dyr*dyr + dzr*dzr;
        float dotr = rnb[3*ir]*dxr + rnb[3*ir+1]*dyr + rnb[3*ir+2]*dzr;
        float o2h = sqrtf(d2r) * sgnf(dotr);
        bool interior = (-dotr) > 0.f;

        float dxg = ox - gb[3*ig], dyg = oy - gb[3*ig+1], dzg = oz - gb[3*ig+2];
        float d2g = dxg*dxg + dyg*dyg + dzg*dzg;
        float dotg = gnb[3*ig]*dxg + gnb[3*ig+1]*dyg + gnb[3*ig+2]*dzg;
        float o2h_gt = sqrtf(d2g) * sgnf(dotg);

        float d2p = fmaxf(2.f * mp, 0.f);
        bool cmap  = sqrtf(d2g) < 0.005f;
        bool rcmap = sqrtf(d2r) < 0.005f;

        a[0] += interior ? d2r : 0.f;
        a[1] += cmap ? 1.f : 0.f;
        a[2] += cmap ? d2p : 0.f;
        a[3] += (cmap && rcmap) ? 1.f : 0.f;
        bool w_dist = (o2h_gt < 0.01f) && (o2h_gt > -0.005f);
        float w = (o2h < 0.f) ? 1.5f : (w_dist ? 1.0f : 0.1f);
        a[4] += fabsf(o2h - o2h_gt) * w;
    }
    block_acc(a, 5, 0, red, tid);
}

__device__ void hand_epilogue(int b, const float* __restrict__ vw,
                              float (*red)[8], int tid)
{
    float s = 0.f;
    for (int i = tid; i < NT_PAD; i += 256) {
        const int base = b * NT_PAD + i;
        float mr = __uint_as_float(~g_cmr[base]);
        float mg = __uint_as_float(~g_cmg[base]);
        g_cmr[base] = 0u;
        g_cmg[base] = 0u;
        if (i < NH) {
            float dr = sqrtf(fmaxf(2.f * mr, 0.f));
            float dg = sqrtf(fmaxf(2.f * mg, 0.f));
            s += fabsf(dr - dg) * powf(vw[i], 0.4f);
        }
    }
    float v[1] = { s };
    block_acc(v, 1, 5, red, tid);
}

__global__ void __launch_bounds__(256, 4) k_all(
    const float* __restrict__ recon, const float* __restrict__ gt,
    const float* __restrict__ recon_n, const float* __restrict__ gt_n,
    const float* __restrict__ obj,
    const float* __restrict__ mean, const float* __restrict__ logv,
    const float* __restrict__ vw, float* __restrict__ out)
{
    __shared__ __align__(16) u64 T[PRIOR_PAD][4];
    __shared__ __align__(8) uint2 s_cm[8][FUS_SEGLEN];
    __shared__ float red[8][8];
    __shared__ int s_elect;   // bit0: obj epi, bit1: hand epi, bit2: final
    const int tid = threadIdx.x;
    const int lane = tid & 31, warp = tid >> 5;
    const float FINF = __int_as_float(0x7F800000);
    const int item = blockIdx.x;

    int my_b, my_chunk;
    bool is_fused = (item >= PRIOR_ITEMS);

    if (is_fused) {
        // ===== FUSED: row argmin + col min =====
        const int fit   = item - PRIOR_ITEMS;
        const int seg   = fit & 7;
        const int rest  = fit >> 3;
        const int chunk = rest % FUS_CHUNKS;
        const int b     = rest / FUS_CHUNKS;
        my_b = b; my_chunk = chunk;
        const int j0 = chunk * 512 + tid;
        const int j1 = j0 + 256;
        const bool a0 = (j0 < NO), a1 = (j1 < NO);
        const int jj0 = a0 ? j0 : (NO - 1);
        const int jj1 = a1 ? j1 : (NO - 1);

        const float* ob = obj + (size_t)b * NO * 3;
        const float ox0 = ob[3*jj0], oy0 = ob[3*jj0+1], oz0 = ob[3*jj0+2];
        const float ox1 = ob[3*jj1], oy1 = ob[3*jj1+1], oz1 = ob[3*jj1+2];
        const float bq0 = 0.5f*(ox0*ox0 + oy0*oy0 + oz0*oz0);
        const float bq1 = 0.5f*(ox1*ox1 + oy1*oy1 + oz1*oz1);

        const u64 BQ0 = pack2(bq0, bq0), NX0 = pack2(-ox0, -ox0),
                  NY0 = pack2(-oy0, -oy0), NZ0 = pack2(-oz0, -oz0);
        const u64 BQ1 = pack2(bq1, bq1), NX1 = pack2(-ox1, -ox1),
                  NY1 = pack2(-oy1, -oy1), NZ1 = pack2(-oz1, -oz1);

        const float* rb = recon + (size_t)b * NH * 3;
        const float* gb = gt    + (size_t)b * NH * 3;
        const int t0 = seg * FUS_SEGLEN;

        if (tid < FUS_SEGLEN) {
            const int tg = t0 + tid;
            float rx=0.f, ry=0.f, rz=0.f, rw=FINF, gx=0.f, gy=0.f, gz=0.f, gw=FINF;
            if (tg < NH) {
                rx = rb[3*tg]; ry = rb[3*tg+1]; rz = rb[3*tg+2];
                rw = 0.5f*(rx*rx + ry*ry + rz*rz);
                gx = gb[3*tg]; gy = gb[3*tg+1]; gz = gb[3*tg+2];
                gw = 0.5f*(gx*gx + gy*gy + gz*gz);
            }
            float2* pp = (float2*)T[tid];
            pp[0] = make_float2(rx, gx); pp[1] = make_float2(ry, gy);
            pp[2] = make_float2(rz, gz); pp[3] = make_float2(rw, gw);
        }
        __syncthreads();

        unsigned br0 = 0xFFFFFFFFu, bg0 = 0xFFFFFFFFu;
        unsigned br1 = 0xFFFFFFFFu, bg1 = 0xFFFFFFFFu;
#pragma unroll 4
        for (int k = 0; k < FUS_SEGLEN; k++) {
            const ulonglong2 A  = *(const ulonglong2*)&T[k][0];
            const ulonglong2 Bv = *(const ulonglong2*)&T[k][2];
            const unsigned kb = (unsigned)(t0 + k);
            u64 M0 = add2(BQ0, Bv.y);
            M0 = fma2(NX0, A.x, M0); M0 = fma2(NY0, A.y, M0); M0 = fma2(NZ0, Bv.x, M0);
            unsigned r0, g0; unpack2u(M0, r0, g0);
            br0 = min(br0, (r0 & 0xFFFFFC00u) | kb);
            bg0 = min(bg0, (g0 & 0xFFFFFC00u) | kb);
            u64 M1 = add2(BQ1, Bv.y);
            M1 = fma2(NX1, A.x, M1); M1 = fma2(NY1, A.y, M1); M1 = fma2(NZ1, Bv.x, M1);
            unsigned r1, g1; unpack2u(M1, r1, g1);
            br1 = min(br1, (r1 & 0xFFFFFC00u) | kb);
            bg1 = min(bg1, (g1 & 0xFFFFFC00u) | kb);
            unsigned wr = __reduce_min_sync(0xffffffffu, min(r0, r1));
            unsigned wg = __reduce_min_sync(0xffffffffu, min(g0, g1));
            if (lane == 0) s_cm[warp][k] = make_uint2(wr, wg);
        }
        if (a0) { atomicMax(&g_okr[b * NO + j0], ~br0); atomicMax(&g_okg[b * NO + j0], ~bg0); }
        if (a1) { atomicMax(&g_okr[b * NO + j1], ~br1); atomicMax(&g_okg[b * NO + j1], ~bg1); }

        __syncthreads();
        if (tid < FUS_SEGLEN) {
            uint2 m = s_cm[0][tid];
#pragma unroll
            for (int w = 1; w < 8; w++) {
                uint2 v = s_cm[w][tid];
                m.x = min(m.x, v.x);
                m.y = min(m.y, v.y);
            }
            const int base = b * NT_PAD + t0 + tid;
            atomicMax(&g_cmr[base], ~m.x);
            atomicMax(&g_cmg[base], ~m.y);
        }
    } else {
        // ===== PRIOR + MSE/KLD slices =====
        const int idx   = item;
        const int chunk = idx % FUS_CHUNKS;
        const int b     = idx / FUS_CHUNKS;
        my_b = b; my_chunk = chunk;
        const int j0 = chunk * 512 + tid;
        const int j1 = j0 + 256;
        const bool a0 = (j0 < NO), a1 = (j1 < NO);
        const int jj0 = a0 ? j0 : (NO - 1);
        const int jj1 = a1 ? j1 : (NO - 1);

        const float* ob = obj + (size_t)b * NO * 3;
        const float ox0 = ob[3*jj0], oy0 = ob[3*jj0+1], oz0 = ob[3*jj0+2];
        const float ox1 = ob[3*jj1], oy1 = ob[3*jj1+1], oz1 = ob[3*jj1+2];
        const float bq0 = 0.5f*(ox0*ox0 + oy0*oy0 + oz0*oz0);
        const float bq1 = 0.5f*(ox1*ox1 + oy1*oy1 + oz1*oz1);
        const u64 BQP = pack2(bq0, bq1), NXP = pack2(-ox0, -ox1),
                  NYP = pack2(-oy0, -oy1), NZP = pack2(-oz0, -oz1);

        const float* rb = recon + (size_t)b * NH * 3;
        if (tid < PRIOR_PAD) {
            float x = 0.f, y = 0.f, z = 0.f, w = FINF;
            if (tid < NPRIOR) {
                const int p = c_prior[tid];
                x = rb[3*p]; y = rb[3*p+1]; z = rb[3*p+2];
                w = 0.5f*(x*x + y*y + z*z);
            }
            float2* pp = (float2*)T[tid];
            pp[0] = make_float2(x, x); pp[1] = make_float2(y, y);
            pp[2] = make_float2(z, z); pp[3] = make_float2(w, w);
        }
        __syncthreads();

        float mp0 = FINF, mp1 = FINF;
#pragma unroll 8
        for (int k = 0; k < PRIOR_PAD; k++) {
            const ulonglong2 A  = *(const ulonglong2*)&T[k][0];
            const ulonglong2 Bv = *(const ulonglong2*)&T[k][2];
            u64 M = add2(BQP, Bv.y);
            M = fma2(NXP, A.x, M); M = fma2(NYP, A.y, M); M = fma2(NZP, Bv.x, M);
            unsigned u0, u1; unpack2u(M, u0, u1);
            mp0 = fminf(mp0, __uint_as_float(u0));
            mp1 = fminf(mp1, __uint_as_float(u1));
        }
        if (a0) g_mp[b * NO + j0] = mp0;
        if (a1) g_mp[b * NO + j1] = mp1;

        // MSE / KLD slices
        float v[2] = {0.f, 0.f};
        {
            const int base = item * MSE_PER_BLK;
            for (int q = base + (tid >> 1); q < base + MSE_PER_BLK && q < MSE_ITEMS; q += 128) {
                // 2 threads per item? no — simple: tid strides over MSE_PER_BLK items
            }
            // straightforward strided loop
            for (int q = base + tid; q < base + MSE_PER_BLK && q < MSE_ITEMS; q += 256) {
                const float4 r4 = ((const float4*)recon)[q];
                const float4 g4 = ((const float4*)gt)[q];
                float d0 = r4.x - g4.x, d1 = r4.y - g4.y, d2 = r4.z - g4.z, d3 = r4.w - g4.w;
                v[0] += d0*d0 + d1*d1 + d2*d2 + d3*d3;
            }
            const int kbase = item * KLD_PER_BLK;
            for (int q = kbase + tid; q < kbase + KLD_PER_BLK && q < B_ * Z_; q += 256) {
                float m = mean[q], lv = logv[q];
                v[1] += 1.f + lv - m * m - expf(lv);
            }
        }
        block_acc(v, 2, 6, red, tid);
    }

    // ===== elections =====
    __syncthreads();
    if (tid == 0) {
        __threadfence();
        int e = 0;
        unsigned c = atomicAdd(&g_done_chunk[my_b * FUS_CHUNKS + my_chunk], 1u);
        if (c == 8u) e |= 1;
        if (is_fused) {
            unsigned t = atomicAdd(&g_done_batch[my_b], 1u);
            if (t == 47u) e |= 2;
        }
        s_elect = e;
    }
    __syncthreads();
    const int elect = s_elect;

    if (elect & 1) {
        __threadfence();
        obj_epilogue(my_b, my_chunk, recon, gt, recon_n, gt_n, obj, red, tid);
    }
    if (elect & 2) {
        __threadfence();
        hand_epilogue(my_b, vw, red, tid);
    }

    __syncthreads();
    if (tid == 0) {
        __threadfence();
        unsigned g = atomicAdd(&g_done_all, 1u);
        if (g == (unsigned)(TOTAL_ITEMS - 1)) {
            __threadfence();
            const double KLC = 0.005;
            double recon_loss = g_acc[6] / B_;
            double kld        = -0.5 * g_acc[7] / B_ * 10.0;
            double penetr     = 100.0 * g_acc[0] / B_;
            double npts       = g_acc[1];
            double contact    = 3000.0 * ((npts > 0.0) ? (g_acc[2] / (B_ * npts)) : 0.0);
            double consist    = -5.0 * g_acc[3] / (npts + 0.0001);
            double loss_o     = 30.0 * (1.0 - KLC) * g_acc[4] / ((double)B_ * NO);
            double loss_h     = 35.0 * (1.0 - KLC) * g_acc[5] / ((double)B_ * NH);
            double total = recon_loss + 0.1 * kld + 1000.0 * penetr
                         + 10.0 * contact + 10.0 * consist + (loss_h + loss_o);
            out[0] = (float)total;
            // reset for next graph replay
            for (int q = 0; q < 8; q++) g_acc[q] = 0.0;
            for (int q = 0; q < B_ * FUS_CHUNKS; q++) g_done_chunk[q] = 0u;
            for (int q = 0; q < B_; q++) g_done_batch[q] = 0u;
            g_done_all = 0u;
        }
    }
}

extern "C" void kernel_launch(void* const* d_in, const int* in_sizes, int n_in,
                              void* d_out, int out_size) {
    const float* recon   = (const float*)d_in[0];
    const float* gt      = (const float*)d_in[1];
    const float* recon_n = (const float*)d_in[2];
    const float* gt_n    = (const float*)d_in[3];
    const float* obj     = (const float*)d_in[4];
    const float* mean    = (const float*)d_in[5];
    const float* logv    = (const float*)d_in[6];
    const float* vw      = (const float*)d_in[7];
    float* out = (float*)d_out;

    k_all<<<TOTAL_ITEMS, 256>>>(recon, gt, recon_n, gt_n, obj, mean, logv, vw, out);
}

// round 13
// speedup vs baseline: 1.0967x; 1.0967x over previous
#include <cuda_runtime.h>
#include <math.h>

#define B_  32
#define NH  778
#define NO  3000
#define Z_  64
#define NPRIOR 204

#define NT_PAD      800
#define FUS_SEGS    8
#define FUS_SEGLEN  100
#define FUS_CHUNKS  3          // 3*1024 = 3072 >= 3000 (4 queries/thread)
#define FUS_ITEMS   (FUS_SEGS * FUS_CHUNKS * B_)    // 768
#define PRIOR_PAD   208
#define PRIOR_ITEMS (FUS_CHUNKS * B_)               // 96 (first: longest blocks)
#define TOTAL_ITEMS (FUS_ITEMS + PRIOR_ITEMS)       // 864

#define EPI_MSE_BLOCKS  73
#define EPI_KLD_BLOCKS  8
#define EPI_OBJ_BLOCKS  375
#define EPI_HAND_BLOCKS 98
#define EPI_TOTAL (EPI_MSE_BLOCKS + EPI_KLD_BLOCKS + EPI_OBJ_BLOCKS + EPI_HAND_BLOCKS) // 554

// Merged via atomicMax(~bits): zero = identity; consumers reset to 0 for replay.
__device__ unsigned g_okr[B_ * NO];
__device__ unsigned g_okg[B_ * NO];
__device__ float    g_mp[B_ * NO];
__device__ unsigned g_cmr[B_ * NT_PAD];
__device__ unsigned g_cmg[B_ * NT_PAD];
__device__ float    g_epart[EPI_TOTAL][8];
__device__ unsigned g_ctr;

__constant__ int c_prior[NPRIOR] = {
  697,698,699,700,712,713,714,715,737,738,739,740,741,743,744,745,
  746,748,749,750,753,754,755,756,757,758,759,760,761,762,763,764,
  765,766,767,768,
  46,47,48,49,164,165,166,167,194,195,223,237,238,280,281,298,
  301,317,320,323,324,325,326,327,328,329,330,331,332,333,340,341,
  342,343,344,345,346,347,348,349,350,351,352,353,354,355,
  356,357,358,359,375,376,386,387,396,397,402,403,413,429,433,434,
  435,436,437,438,439,440,441,442,443,444,452,453,454,455,456,459,
  460,461,462,463,464,465,466,467,
  468,469,470,471,484,485,486,496,497,506,507,513,514,524,545,546,
  547,548,549,550,551,552,553,555,563,564,565,566,567,570,572,573,
  574,575,576,577,578,
  580,581,582,583,600,601,602,614,615,624,625,630,631,641,663,664,
  665,666,667,668,670,672,680,681,682,683,684,686,687,688,689,690,
  691,692,693,694,695,
  73,96,98,99,772,774,775,777
};

typedef unsigned long long u64;

__device__ __forceinline__ u64 fma2(u64 a, u64 b, u64 c) {
    u64 d;
    asm("fma.rn.f32x2 %0, %1, %2, %3;" : "=l"(d) : "l"(a), "l"(b), "l"(c));
    return d;
}
__device__ __forceinline__ u64 add2(u64 a, u64 b) {
    u64 d;
    asm("add.rn.f32x2 %0, %1, %2;" : "=l"(d) : "l"(a), "l"(b));
    return d;
}
__device__ __forceinline__ u64 pack2(float lo, float hi) {
    u64 d;
    asm("mov.b64 %0, {%1, %2};" : "=l"(d) : "r"(__float_as_uint(lo)), "r"(__float_as_uint(hi)));
    return d;
}
__device__ __forceinline__ void unpack2u(u64 v, unsigned& lo, unsigned& hi) {
    asm("mov.b64 {%0, %1}, %2;" : "=r"(lo), "=r"(hi) : "l"(v));
}
__device__ __forceinline__ float warp_sum(float v) {
#pragma unroll
    for (int o = 16; o > 0; o >>= 1) v += __shfl_down_sync(0xffffffffu, v, o);
    return v;
}
__device__ __forceinline__ float sgnf(float x) {
    return (x > 0.f) ? 1.f : ((x < 0.f) ? -1.f : 0.f);
}

__global__ void __launch_bounds__(256, 3) k_main(
    const float* __restrict__ recon, const float* __restrict__ gt,
    const float* __restrict__ obj)
{
    __shared__ __align__(16) u64 T[PRIOR_PAD][4];
    __shared__ __align__(8) uint2 s_cm[8][FUS_SEGLEN];
    const int tid = threadIdx.x;
    const int lane = tid & 31, warp = tid >> 5;
    const float FINF = __int_as_float(0x7F800000);
    const int item = blockIdx.x;

    if (item >= PRIOR_ITEMS) {
        // ===== FUSED: row argmin + col min, 4 queries/thread =====
        const int fit   = item - PRIOR_ITEMS;
        const int seg   = fit & 7;
        const int rest  = fit >> 3;
        const int chunk = rest % FUS_CHUNKS;
        const int b     = rest / FUS_CHUNKS;

        int  jq[4];
        bool aq[4];
        u64 BQ[4], NX[4], NY[4], NZ[4];
        const float* ob = obj + (size_t)b * NO * 3;
#pragma unroll
        for (int q = 0; q < 4; q++) {
            const int j = chunk * 1024 + q * 256 + tid;
            jq[q] = j;
            aq[q] = (j < NO);
            const int jj = aq[q] ? j : (NO - 1);
            const float ox = ob[3*jj], oy = ob[3*jj+1], oz = ob[3*jj+2];
            const float bq = 0.5f*(ox*ox + oy*oy + oz*oz);
            BQ[q] = pack2(bq, bq);
            NX[q] = pack2(-ox, -ox);
            NY[q] = pack2(-oy, -oy);
            NZ[q] = pack2(-oz, -oz);
        }

        const float* rb = recon + (size_t)b * NH * 3;
        const float* gb = gt    + (size_t)b * NH * 3;
        const int t0 = seg * FUS_SEGLEN;

        if (tid < FUS_SEGLEN) {
            const int tg = t0 + tid;
            float rx=0.f, ry=0.f, rz=0.f, rw=FINF, gx=0.f, gy=0.f, gz=0.f, gw=FINF;
            if (tg < NH) {
                rx = rb[3*tg]; ry = rb[3*tg+1]; rz = rb[3*tg+2];
                rw = 0.5f*(rx*rx + ry*ry + rz*rz);
                gx = gb[3*tg]; gy = gb[3*tg+1]; gz = gb[3*tg+2];
                gw = 0.5f*(gx*gx + gy*gy + gz*gz);
            }
            float2* pp = (float2*)T[tid];
            pp[0] = make_float2(rx, gx); pp[1] = make_float2(ry, gy);
            pp[2] = make_float2(rz, gz); pp[3] = make_float2(rw, gw);
        }
        __syncthreads();

        unsigned br[4] = {0xFFFFFFFFu, 0xFFFFFFFFu, 0xFFFFFFFFu, 0xFFFFFFFFu};
        unsigned bg[4] = {0xFFFFFFFFu, 0xFFFFFFFFu, 0xFFFFFFFFu, 0xFFFFFFFFu};
#pragma unroll 4
        for (int k = 0; k < FUS_SEGLEN; k++) {
            const ulonglong2 A  = *(const ulonglong2*)&T[k][0];
            const ulonglong2 Bv = *(const ulonglong2*)&T[k][2];
            const unsigned kb = (unsigned)(t0 + k);
            unsigned cr = 0xFFFFFFFFu, cg = 0xFFFFFFFFu;
#pragma unroll
            for (int q = 0; q < 4; q++) {
                u64 M = add2(BQ[q], Bv.y);
                M = fma2(NX[q], A.x, M); M = fma2(NY[q], A.y, M); M = fma2(NZ[q], Bv.x, M);
                unsigned r, g; unpack2u(M, r, g);
                br[q] = min(br[q], (r & 0xFFFFFC00u) | kb);
                bg[q] = min(bg[q], (g & 0xFFFFFC00u) | kb);
                cr = min(cr, r);
                cg = min(cg, g);
            }
            unsigned wr = __reduce_min_sync(0xffffffffu, cr);
            unsigned wg = __reduce_min_sync(0xffffffffu, cg);
            if (lane == 0) s_cm[warp][k] = make_uint2(wr, wg);
        }
#pragma unroll
        for (int q = 0; q < 4; q++) {
            if (aq[q]) {
                atomicMax(&g_okr[b * NO + jq[q]], ~br[q]);
                atomicMax(&g_okg[b * NO + jq[q]], ~bg[q]);
            }
        }

        __syncthreads();
        if (tid < FUS_SEGLEN) {
            uint2 m = s_cm[0][tid];
#pragma unroll
            for (int w = 1; w < 8; w++) {
                uint2 v = s_cm[w][tid];
                m.x = min(m.x, v.x);
                m.y = min(m.y, v.y);
            }
            const int base = b * NT_PAD + t0 + tid;
            atomicMax(&g_cmr[base], ~m.x);
            atomicMax(&g_cmg[base], ~m.y);
        }
    } else {
        // ===== PRIOR: 204 targets, 1024 queries (4/thread, 2 packed streams) =====
        const int idx   = item;
        const int chunk = idx % FUS_CHUNKS;
        const int b     = idx / FUS_CHUNKS;

        int  jq[4];
        bool aq[4];
        float oxq[4], oyq[4], ozq[4], bqq[4];
        const float* ob = obj + (size_t)b * NO * 3;
#pragma unroll
        for (int q = 0; q < 4; q++) {
            const int j = chunk * 1024 + q * 256 + tid;
            jq[q] = j;
            aq[q] = (j < NO);
            const int jj = aq[q] ? j : (NO - 1);
            oxq[q] = ob[3*jj]; oyq[q] = ob[3*jj+1]; ozq[q] = ob[3*jj+2];
            bqq[q] = 0.5f*(oxq[q]*oxq[q] + oyq[q]*oyq[q] + ozq[q]*ozq[q]);
        }
        const u64 BQ01 = pack2(bqq[0], bqq[1]), NX01 = pack2(-oxq[0], -oxq[1]),
                  NY01 = pack2(-oyq[0], -oyq[1]), NZ01 = pack2(-ozq[0], -ozq[1]);
        const u64 BQ23 = pack2(bqq[2], bqq[3]), NX23 = pack2(-oxq[2], -oxq[3]),
                  NY23 = pack2(-oyq[2], -oyq[3]), NZ23 = pack2(-ozq[2], -ozq[3]);

        const float* rb = recon + (size_t)b * NH * 3;
        if (tid < PRIOR_PAD) {
            float x = 0.f, y = 0.f, z = 0.f, w = FINF;
            if (tid < NPRIOR) {
                const int p = c_prior[tid];
                x = rb[3*p]; y = rb[3*p+1]; z = rb[3*p+2];
                w = 0.5f*(x*x + y*y + z*z);
            }
            float2* pp = (float2*)T[tid];
            pp[0] = make_float2(x, x); pp[1] = make_float2(y, y);
            pp[2] = make_float2(z, z); pp[3] = make_float2(w, w);
        }
        __syncthreads();

        float mp[4] = {FINF, FINF, FINF, FINF};
#pragma unroll 8
        for (int k = 0; k < PRIOR_PAD; k++) {
            const ulonglong2 A  = *(const ulonglong2*)&T[k][0];
            const ulonglong2 Bv = *(const ulonglong2*)&T[k][2];
            u64 M = add2(BQ01, Bv.y);
            M = fma2(NX01, A.x, M); M = fma2(NY01, A.y, M); M = fma2(NZ01, Bv.x, M);
            unsigned u0, u1; unpack2u(M, u0, u1);
            mp[0] = fminf(mp[0], __uint_as_float(u0));
            mp[1] = fminf(mp[1], __uint_as_float(u1));
            M = add2(BQ23, Bv.y);
            M = fma2(NX23, A.x, M); M = fma2(NY23, A.y, M); M = fma2(NZ23, Bv.x, M);
            unpack2u(M, u0, u1);
            mp[2] = fminf(mp[2], __uint_as_float(u0));
            mp[3] = fminf(mp[3], __uint_as_float(u1));
        }
#pragma unroll
        for (int q = 0; q < 4; q++)
            if (aq[q]) g_mp[b * NO + jq[q]] = mp[q];
    }
}

// Epilogue (identical structure to R11): MSE/KLD first; OBJ/HAND consume + reset.
__global__ void __launch_bounds__(256) k_epi(
    const float* __restrict__ recon, const float* __restrict__ gt,
    const float* __restrict__ recon_n, const float* __restrict__ gt_n,
    const float* __restrict__ obj,
    const float* __restrict__ mean, const float* __restrict__ logv,
    const float* __restrict__ vw, float* __restrict__ out)
{
    const int tid = threadIdx.x;
    const int blk = blockIdx.x;

    float a[8] = {0.f,0.f,0.f,0.f,0.f,0.f,0.f,0.f};

    if (blk < EPI_MSE_BLOCKS) {
        const int q = blk * 256 + tid;
        if (q < (B_ * NH * 3) / 4) {
            const float4 r4 = ((const float4*)recon)[q];
            const float4 g4 = ((const float4*)gt)[q];
            float d0 = r4.x - g4.x, d1 = r4.y - g4.y, d2 = r4.z - g4.z, d3 = r4.w - g4.w;
            a[6] = d0*d0 + d1*d1 + d2*d2 + d3*d3;
        }
    } else if (blk < EPI_MSE_BLOCKS + EPI_KLD_BLOCKS) {
        const int q = (blk - EPI_MSE_BLOCKS) * 256 + tid;
        float m = mean[q], lv = logv[q];
        a[7] = 1.f + lv - m * m - expf(lv);
    } else if (blk < EPI_MSE_BLOCKS + EPI_KLD_BLOCKS + EPI_OBJ_BLOCKS) {
        const int idx = (blk - EPI_MSE_BLOCKS - EPI_KLD_BLOCKS) * 256 + tid;
        const int b = idx / NO;
        const int j = idx - b * NO;
        const unsigned br = ~g_okr[idx];
        const unsigned bg = ~g_okg[idx];
        const float mp = g_mp[idx];
        g_okr[idx] = 0u;
        g_okg[idx] = 0u;

        const float* ob = obj + (size_t)b * NO * 3;
        const float ox = ob[3*j], oy = ob[3*j+1], oz = ob[3*j+2];
        const int ir = (int)(br & 1023u);
        const int ig = (int)(bg & 1023u);

        const float* rb  = recon   + (size_t)b * NH * 3;
        const float* gb  = gt      + (size_t)b * NH * 3;
        const float* rnb = recon_n + (size_t)b * NH * 3;
        const float* gnb = gt_n    + (size_t)b * NH * 3;

        float dxr = ox - rb[3*ir], dyr = oy - rb[3*ir+1], dzr = oz - rb[3*ir+2];
        float d2r = dxr*dxr + dyr*dyr + dzr*dzr;
        float dotr = rnb[3*ir]*dxr + rnb[3*ir+1]*dyr + rnb[3*ir+2]*dzr;
        float o2h = sqrtf(d2r) * sgnf(dotr);
        bool interior = (-dotr) > 0.f;

        float dxg = ox - gb[3*ig], dyg = oy - gb[3*ig+1], dzg = oz - gb[3*ig+2];
        float d2g = dxg*dxg + dyg*dyg + dzg*dzg;
        float dotg = gnb[3*ig]*dxg + gnb[3*ig+1]*dyg + gnb[3*ig+2]*dzg;
        float o2h_gt = sqrtf(d2g) * sgnf(dotg);

        float d2p = fmaxf(2.f * mp, 0.f);
        bool cmap  = sqrtf(d2g) < 0.005f;
        bool rcmap = sqrtf(d2r) < 0.005f;

        a[0] = interior ? d2r : 0.f;
        a[1] = cmap ? 1.f : 0.f;
        a[2] = cmap ? d2p : 0.f;
        a[3] = (cmap && rcmap) ? 1.f : 0.f;
        bool w_dist = (o2h_gt < 0.01f) && (o2h_gt > -0.005f);
        float w = (o2h < 0.f) ? 1.5f : (w_dist ? 1.0f : 0.1f);
        a[4] = fabsf(o2h - o2h_gt) * w;
    } else {
        const int j = (blk - EPI_MSE_BLOCKS - EPI_KLD_BLOCKS - EPI_OBJ_BLOCKS) * 256 + tid;
        if (j < B_ * NH) {
            const int b = j / NH;
            const int i = j - b * NH;
            const int base = b * NT_PAD + i;
            float mr = __uint_as_float(~g_cmr[base]);
            float mg = __uint_as_float(~g_cmg[base]);
            g_cmr[base] = 0u;
            g_cmg[base] = 0u;
            float dr = sqrtf(fmaxf(2.f * mr, 0.f));
            float dg = sqrtf(fmaxf(2.f * mg, 0.f));
            a[5] = fabsf(dr - dg) * powf(vw[i], 0.4f);
        }
    }

    __shared__ float red[8][8];
    __shared__ bool s_last;
    const int lane = tid & 31, warp = tid >> 5;
#pragma unroll
    for (int q = 0; q < 8; q++) {
        float v = warp_sum(a[q]);
        if (lane == 0) red[warp][q] = v;
    }
    __syncthreads();
    if (tid < 8) {
        float s = 0.f;
#pragma unroll
        for (int wi = 0; wi < 8; wi++) s += red[wi][tid];
        g_epart[blk][tid] = s;
    }
    if (tid == 0) {
        __threadfence();
        unsigned t = atomicAdd(&g_ctr, 1u);
        s_last = (t == (unsigned)(gridDim.x - 1));
    }
    __syncthreads();

    if (s_last) {
        __threadfence();
        float p[8] = {0.f,0.f,0.f,0.f,0.f,0.f,0.f,0.f};
        for (int i = tid; i < EPI_TOTAL; i += 256) {
#pragma unroll
            for (int q = 0; q < 8; q++) p[q] += g_epart[i][q];
        }
#pragma unroll
        for (int q = 0; q < 8; q++) {
            float v = warp_sum(p[q]);
            if (lane == 0) red[warp][q] = v;
        }
        __syncthreads();
        if (tid == 0) {
            double acc[8];
#pragma unroll
            for (int q = 0; q < 8; q++) {
                float s = 0.f;
                for (int wi = 0; wi < 8; wi++) s += red[wi][q];
                acc[q] = (double)s;
            }
            const double KLC = 0.005;
            double recon_loss = acc[6] / B_;
            double kld        = -0.5 * acc[7] / B_ * 10.0;
            double penetr     = 100.0 * acc[0] / B_;
            double npts       = acc[1];
            double contact    = 3000.0 * ((npts > 0.0) ? (acc[2] / (B_ * npts)) : 0.0);
            double consist    = -5.0 * acc[3] / (npts + 0.0001);
            double loss_o     = 30.0 * (1.0 - KLC) * acc[4] / ((double)B_ * NO);
            double loss_h     = 35.0 * (1.0 - KLC) * acc[5] / ((double)B_ * NH);
            double total = recon_loss + 0.1 * kld + 1000.0 * penetr
                         + 10.0 * contact + 10.0 * consist + (loss_h + loss_o);
            out[0] = (float)total;
            g_ctr = 0u;
        }
    }
}

extern "C" void kernel_launch(void* const* d_in, const int* in_sizes, int n_in,
                              void* d_out, int out_size) {
    const float* recon   = (const float*)d_in[0];
    const float* gt      = (const float*)d_in[1];
    const float* recon_n = (const float*)d_in[2];
    const float* gt_n    = (const float*)d_in[3];
    const float* obj     = (const float*)d_in[4];
    const float* mean    = (const float*)d_in[5];
    const float* logv    = (const float*)d_in[6];
    const float* vw      = (const float*)d_in[7];
    float* out = (float*)d_out;

    k_main<<<TOTAL_ITEMS, 256>>>(recon, gt, obj);
    k_epi<<<EPI_TOTAL, 256>>>(recon, gt, recon_n, gt_n, obj, mean, logv, vw, out);
}

// round 14
// speedup vs baseline: 1.1030x; 1.0057x over previous
#include <cuda_runtime.h>
#include <cooperative_groups.h>
#include <math.h>

namespace cg = cooperative_groups;

#define B_  32
#define NH  778
#define NO  3000
#define Z_  64
#define NPRIOR 204

#define NT_PAD      800
#define FUS_SEGS    8
#define FUS_SEGLEN  100
#define FUS_CHUNKS  3          // 3*1024 = 3072 >= 3000 (4 queries/thread)
#define FUS_ITEMS   (FUS_SEGS * FUS_CHUNKS * B_)    // 768
#define PRIOR_PAD   208
#define PRIOR_ITEMS (FUS_CHUNKS * B_)               // 96 (first: longest)
#define SCAN_ITEMS  (FUS_ITEMS + PRIOR_ITEMS)       // 864

#define GRID_BLOCKS 432        // 2 scan items per block; must be co-resident (3/SM)

#define EPI_MSE_BLOCKS  73
#define EPI_KLD_BLOCKS  8
#define EPI_OBJ_BLOCKS  375
#define EPI_HAND_BLOCKS 98
#define EPI_ITEMS (EPI_MSE_BLOCKS + EPI_KLD_BLOCKS + EPI_OBJ_BLOCKS + EPI_HAND_BLOCKS) // 554

// Merged via atomicMax(~bits): zero = identity; consumers reset to 0 for replay.
__device__ unsigned g_okr[B_ * NO];
__device__ unsigned g_okg[B_ * NO];
__device__ float    g_mp[B_ * NO];
__device__ unsigned g_cmr[B_ * NT_PAD];
__device__ unsigned g_cmg[B_ * NT_PAD];
// 0 penetr, 1 npts, 2 contact, 3 consist, 4 loss_o, 5 loss_h, 6 mse, 7 kld
__device__ double   g_acc[8];

__constant__ int c_prior[NPRIOR] = {
  697,698,699,700,712,713,714,715,737,738,739,740,741,743,744,745,
  746,748,749,750,753,754,755,756,757,758,759,760,761,762,763,764,
  765,766,767,768,
  46,47,48,49,164,165,166,167,194,195,223,237,238,280,281,298,
  301,317,320,323,324,325,326,327,328,329,330,331,332,333,340,341,
  342,343,344,345,346,347,348,349,350,351,352,353,354,355,
  356,357,358,359,375,376,386,387,396,397,402,403,413,429,433,434,
  435,436,437,438,439,440,441,442,443,444,452,453,454,455,456,459,
  460,461,462,463,464,465,466,467,
  468,469,470,471,484,485,486,496,497,506,507,513,514,524,545,546,
  547,548,549,550,551,552,553,555,563,564,565,566,567,570,572,573,
  574,575,576,577,578,
  580,581,582,583,600,601,602,614,615,624,625,630,631,641,663,664,
  665,666,667,668,670,672,680,681,682,683,684,686,687,688,689,690,
  691,692,693,694,695,
  73,96,98,99,772,774,775,777
};

typedef unsigned long long u64;

__device__ __forceinline__ u64 fma2(u64 a, u64 b, u64 c) {
    u64 d;
    asm("fma.rn.f32x2 %0, %1, %2, %3;" : "=l"(d) : "l"(a), "l"(b), "l"(c));
    return d;
}
__device__ __forceinline__ u64 add2(u64 a, u64 b) {
    u64 d;
    asm("add.rn.f32x2 %0, %1, %2;" : "=l"(d) : "l"(a), "l"(b));
    return d;
}
__device__ __forceinline__ u64 pack2(float lo, float hi) {
    u64 d;
    asm("mov.b64 %0, {%1, %2};" : "=l"(d) : "r"(__float_as_uint(lo)), "r"(__float_as_uint(hi)));
    return d;
}
__device__ __forceinline__ void unpack2u(u64 v, unsigned& lo, unsigned& hi) {
    asm("mov.b64 {%0, %1}, %2;" : "=r"(lo), "=r"(hi) : "l"(v));
}
__device__ __forceinline__ float warp_sum(float v) {
#pragma unroll
    for (int o = 16; o > 0; o >>= 1) v += __shfl_down_sync(0xffffffffu, v, o);
    return v;
}
__device__ __forceinline__ float sgnf(float x) {
    return (x > 0.f) ? 1.f : ((x < 0.f) ? -1.f : 0.f);
}

struct Smem {
    u64 T[PRIOR_PAD][4];
    uint2 s_cm[8][FUS_SEGLEN];
    float red[8][8];
};

__device__ __forceinline__ void block_acc(float* vals, int n, int accbase,
                                          Smem* S, int tid) {
    const int lane = tid & 31, warp = tid >> 5;
    for (int q = 0; q < n; q++) {
        float v = warp_sum(vals[q]);
        if (lane == 0) S->red[warp][q] = v;
    }
    __syncthreads();
    if (tid < n) {
        float s = 0.f;
#pragma unroll
        for (int wi = 0; wi < 8; wi++) s += S->red[wi][tid];
        atomicAdd(&g_acc[accbase + tid], (double)s);
    }
    __syncthreads();
}

__device__ void scan_item(int item, Smem* S,
    const float* __restrict__ recon, const float* __restrict__ gt,
    const float* __restrict__ obj, int tid)
{
    const int lane = tid & 31, warp = tid >> 5;
    const float FINF = __int_as_float(0x7F800000);

    if (item >= PRIOR_ITEMS) {
        const int fit   = item - PRIOR_ITEMS;
        const int seg   = fit & 7;
        const int rest  = fit >> 3;
        const int chunk = rest % FUS_CHUNKS;
        const int b     = rest / FUS_CHUNKS;

        int  jq[4];
        bool aq[4];
        u64 BQ[4], NX[4], NY[4], NZ[4];
        const float* ob = obj + (size_t)b * NO * 3;
#pragma unroll
        for (int q = 0; q < 4; q++) {
            const int j = chunk * 1024 + q * 256 + tid;
            jq[q] = j;
            aq[q] = (j < NO);
            const int jj = aq[q] ? j : (NO - 1);
            const float ox = ob[3*jj], oy = ob[3*jj+1], oz = ob[3*jj+2];
            const float bq = 0.5f*(ox*ox + oy*oy + oz*oz);
            BQ[q] = pack2(bq, bq);
            NX[q] = pack2(-ox, -ox);
            NY[q] = pack2(-oy, -oy);
            NZ[q] = pack2(-oz, -oz);
        }

        const float* rb = recon + (size_t)b * NH * 3;
        const float* gb = gt    + (size_t)b * NH * 3;
        const int t0 = seg * FUS_SEGLEN;

        if (tid < FUS_SEGLEN) {
            const int tg = t0 + tid;
            float rx=0.f, ry=0.f, rz=0.f, rw=FINF, gx=0.f, gy=0.f, gz=0.f, gw=FINF;
            if (tg < NH) {
                rx = rb[3*tg]; ry = rb[3*tg+1]; rz = rb[3*tg+2];
                rw = 0.5f*(rx*rx + ry*ry + rz*rz);
                gx = gb[3*tg]; gy = gb[3*tg+1]; gz = gb[3*tg+2];
                gw = 0.5f*(gx*gx + gy*gy + gz*gz);
            }
            float2* pp = (float2*)S->T[tid];
            pp[0] = make_float2(rx, gx); pp[1] = make_float2(ry, gy);
            pp[2] = make_float2(rz, gz); pp[3] = make_float2(rw, gw);
        }
        __syncthreads();

        unsigned br[4] = {0xFFFFFFFFu, 0xFFFFFFFFu, 0xFFFFFFFFu, 0xFFFFFFFFu};
        unsigned bg[4] = {0xFFFFFFFFu, 0xFFFFFFFFu, 0xFFFFFFFFu, 0xFFFFFFFFu};
#pragma unroll 4
        for (int k = 0; k < FUS_SEGLEN; k++) {
            const ulonglong2 A  = *(const ulonglong2*)&S->T[k][0];
            const ulonglong2 Bv = *(const ulonglong2*)&S->T[k][2];
            const unsigned kb = (unsigned)(t0 + k);
            unsigned cr = 0xFFFFFFFFu, cg = 0xFFFFFFFFu;
#pragma unroll
            for (int q = 0; q < 4; q++) {
                u64 M = add2(BQ[q], Bv.y);
                M = fma2(NX[q], A.x, M); M = fma2(NY[q], A.y, M); M = fma2(NZ[q], Bv.x, M);
                unsigned r, g; unpack2u(M, r, g);
                br[q] = min(br[q], (r & 0xFFFFFC00u) | kb);
                bg[q] = min(bg[q], (g & 0xFFFFFC00u) | kb);
                cr = min(cr, r);
                cg = min(cg, g);
            }
            unsigned wr = __reduce_min_sync(0xffffffffu, cr);
            unsigned wg = __reduce_min_sync(0xffffffffu, cg);
            if (lane == 0) S->s_cm[warp][k] = make_uint2(wr, wg);
        }
#pragma unroll
        for (int q = 0; q < 4; q++) {
            if (aq[q]) {
                atomicMax(&g_okr[b * NO + jq[q]], ~br[q]);
                atomicMax(&g_okg[b * NO + jq[q]], ~bg[q]);
            }
        }

        __syncthreads();
        if (tid < FUS_SEGLEN) {
            uint2 m = S->s_cm[0][tid];
#pragma unroll
            for (int w = 1; w < 8; w++) {
                uint2 v = S->s_cm[w][tid];
                m.x = min(m.x, v.x);
                m.y = min(m.y, v.y);
            }
            const int base = b * NT_PAD + t0 + tid;
            atomicMax(&g_cmr[base], ~m.x);
            atomicMax(&g_cmg[base], ~m.y);
        }
    } else {
        const int chunk = item % FUS_CHUNKS;
        const int b     = item / FUS_CHUNKS;

        int  jq[4];
        bool aq[4];
        float oxq[4], oyq[4], ozq[4], bqq[4];
        const float* ob = obj + (size_t)b * NO * 3;
#pragma unroll
        for (int q = 0; q < 4; q++) {
            const int j = chunk * 1024 + q * 256 + tid;
            jq[q] = j;
            aq[q] = (j < NO);
            const int jj = aq[q] ? j : (NO - 1);
            oxq[q] = ob[3*jj]; oyq[q] = ob[3*jj+1]; ozq[q] = ob[3*jj+2];
            bqq[q] = 0.5f*(oxq[q]*oxq[q] + oyq[q]*oyq[q] + ozq[q]*ozq[q]);
        }
        const u64 BQ01 = pack2(bqq[0], bqq[1]), NX01 = pack2(-oxq[0], -oxq[1]),
                  NY01 = pack2(-oyq[0], -oyq[1]), NZ01 = pack2(-ozq[0], -ozq[1]);
        const u64 BQ23 = pack2(bqq[2], bqq[3]), NX23 = pack2(-oxq[2], -oxq[3]),
                  NY23 = pack2(-oyq[2], -oyq[3]), NZ23 = pack2(-ozq[2], -ozq[3]);

        const float* rb = recon + (size_t)b * NH * 3;
        if (tid < PRIOR_PAD) {
            float x = 0.f, y = 0.f, z = 0.f, w = FINF;
            if (tid < NPRIOR) {
                const int p = c_prior[tid];
                x = rb[3*p]; y = rb[3*p+1]; z = rb[3*p+2];
                w = 0.5f*(x*x + y*y + z*z);
            }
            float2* pp = (float2*)S->T[tid];
            pp[0] = make_float2(x, x); pp[1] = make_float2(y, y);
            pp[2] = make_float2(z, z); pp[3] = make_float2(w, w);
        }
        __syncthreads();

        float mp[4] = {FINF, FINF, FINF, FINF};
#pragma unroll 8
        for (int k = 0; k < PRIOR_PAD; k++) {
            const ulonglong2 A  = *(const ulonglong2*)&S->T[k][0];
            const ulonglong2 Bv = *(const ulonglong2*)&S->T[k][2];
            u64 M = add2(BQ01, Bv.y);
            M = fma2(NX01, A.x, M); M = fma2(NY01, A.y, M); M = fma2(NZ01, Bv.x, M);
            unsigned u0, u1; unpack2u(M, u0, u1);
            mp[0] = fminf(mp[0], __uint_as_float(u0));
            mp[1] = fminf(mp[1], __uint_as_float(u1));
            M = add2(BQ23, Bv.y);
            M = fma2(NX23, A.x, M); M = fma2(NY23, A.y, M); M = fma2(NZ23, Bv.x, M);
            unpack2u(M, u0, u1);
            mp[2] = fminf(mp[2], __uint_as_float(u0));
            mp[3] = fminf(mp[3], __uint_as_float(u1));
        }
#pragma unroll
        for (int q = 0; q < 4; q++)
            if (aq[q]) g_mp[b * NO + jq[q]] = mp[q];
    }
}

__device__ void epi_item(int blk, Smem* S,
    const float* __restrict__ recon, const float* __restrict__ gt,
    const float* __restrict__ recon_n, const float* __restrict__ gt_n,
    const float* __restrict__ obj,
    const float* __restrict__ mean, const float* __restrict__ logv,
    const float* __restrict__ vw, int tid)
{
    if (blk < EPI_MSE_BLOCKS) {
        float v[1] = {0.f};
        const int q = blk * 256 + tid;
        if (q < (B_ * NH * 3) / 4) {
            const float4 r4 = ((const float4*)recon)[q];
            const float4 g4 = ((const float4*)gt)[q];
            float d0 = r4.x - g4.x, d1 = r4.y - g4.y, d2 = r4.z - g4.z, d3 = r4.w - g4.w;
            v[0] = d0*d0 + d1*d1 + d2*d2 + d3*d3;
        }
        block_acc(v, 1, 6, S, tid);
    } else if (blk < EPI_MSE_BLOCKS + EPI_KLD_BLOCKS) {
        float v[1] = {0.f};
        const int q = (blk - EPI_MSE_BLOCKS) * 256 + tid;
        float m = mean[q], lv = logv[q];
        v[0] = 1.f + lv - m * m - expf(lv);
        block_acc(v, 1, 7, S, tid);
    } else if (blk < EPI_MSE_BLOCKS + EPI_KLD_BLOCKS + EPI_OBJ_BLOCKS) {
        float a[5] = {0.f,0.f,0.f,0.f,0.f};
        const int idx = (blk - EPI_MSE_BLOCKS - EPI_KLD_BLOCKS) * 256 + tid;
        const int b = idx / NO;
        const int j = idx - b * NO;
        const unsigned br = ~g_okr[idx];
        const unsigned bg = ~g_okg[idx];
        const float mp = g_mp[idx];
        g_okr[idx] = 0u;
        g_okg[idx] = 0u;

        const float* ob = obj + (size_t)b * NO * 3;
        const float ox = ob[3*j], oy = ob[3*j+1], oz = ob[3*j+2];
        const int ir = (int)(br & 1023u);
        const int ig = (int)(bg & 1023u);

        const float* rb  = recon   + (size_t)b * NH * 3;
        const float* gb  = gt      + (size_t)b * NH * 3;
        const float* rnb = recon_n + (size_t)b * NH * 3;
        const float* gnb = gt_n    + (size_t)b * NH * 3;

        float dxr = ox - rb[3*ir], dyr = oy - rb[3*ir+1], dzr = oz - rb[3*ir+2];
        float d2r = dxr*dxr + dyr*dyr + dzr*dzr;
        float dotr = rnb[3*ir]*dxr + rnb[3*ir+1]*dyr + rnb[3*ir+2]*dzr;
        float o2h = sqrtf(d2r) * sgnf(dotr);
        bool interior = (-dotr) > 0.f;

        float dxg = ox - gb[3*ig], dyg = oy - gb[3*ig+1], dzg = oz - gb[3*ig+2];
        float d2g = dxg*dxg + dyg*dyg + dzg*dzg;
        float dotg = gnb[3*ig]*dxg + gnb[3*ig+1]*dyg + gnb[3*ig+2]*dzg;
        float o2h_gt = sqrtf(d2g) * sgnf(dotg);

        float d2p = fmaxf(2.f * mp, 0.f);
        bool cmap  = sqrtf(d2g) < 0.005f;
        bool rcmap = sqrtf(d2r) < 0.005f;

        a[0] = interior ? d2r : 0.f;
        a[1] = cmap ? 1.f : 0.f;
        a[2] = cmap ? d2p : 0.f;
        a[3] = (cmap && rcmap) ? 1.f : 0.f;
        bool w_dist = (o2h_gt < 0.01f) && (o2h_gt > -0.005f);
        float w = (o2h < 0.f) ? 1.5f : (w_dist ? 1.0f : 0.1f);
        a[4] = fabsf(o2h - o2h_gt) * w;
        block_acc(a, 5, 0, S, tid);
    } else {
        float v[1] = {0.f};
        const int j = (blk - EPI_MSE_BLOCKS - EPI_KLD_BLOCKS - EPI_OBJ_BLOCKS) * 256 + tid;
        if (j < B_ * NH) {
            const int b = j / NH;
            const int i = j - b * NH;
            const int base = b * NT_PAD + i;
            float mr = __uint_as_float(~g_cmr[base]);
            float mg = __uint_as_float(~g_cmg[base]);
            g_cmr[base] = 0u;
            g_cmg[base] = 0u;
            float dr = sqrtf(fmaxf(2.f * mr, 0.f));
            float dg = sqrtf(fmaxf(2.f * mg, 0.f));
            v[0] = fabsf(dr - dg) * powf(vw[i], 0.4f);
        }
        block_acc(v, 1, 5, S, tid);
    }
}

__global__ void __launch_bounds__(256, 3) k_all(
    const float* __restrict__ recon, const float* __restrict__ gt,
    const float* __restrict__ recon_n, const float* __restrict__ gt_n,
    const float* __restrict__ obj,
    const float* __restrict__ mean, const float* __restrict__ logv,
    const float* __restrict__ vw, float* __restrict__ out)
{
    __shared__ __align__(16) Smem S;
    const int tid = threadIdx.x;
    cg::grid_group grid = cg::this_grid();

    // Phase 1: scan items (2 per block)
    for (int item = blockIdx.x; item < SCAN_ITEMS; item += GRID_BLOCKS) {
        scan_item(item, &S, recon, gt, obj, tid);
        __syncthreads();
    }

    grid.sync();

    // Phase 2: epilogue items
    for (int e = blockIdx.x; e < EPI_ITEMS; e += GRID_BLOCKS) {
        epi_item(e, &S, recon, gt, recon_n, gt_n, obj, mean, logv, vw, tid);
    }

    grid.sync();

    // Phase 3: final combine
    if (blockIdx.x == 0 && tid == 0) {
        const double KLC = 0.005;
        double recon_loss = g_acc[6] / B_;
        double kld        = -0.5 * g_acc[7] / B_ * 10.0;
        double penetr     = 100.0 * g_acc[0] / B_;
        double npts       = g_acc[1];
        double contact    = 3000.0 * ((npts > 0.0) ? (g_acc[2] / (B_ * npts)) : 0.0);
        double consist    = -5.0 * g_acc[3] / (npts + 0.0001);
        double loss_o     = 30.0 * (1.0 - KLC) * g_acc[4] / ((double)B_ * NO);
        double loss_h     = 35.0 * (1.0 - KLC) * g_acc[5] / ((double)B_ * NH);
        double total = recon_loss + 0.1 * kld + 1000.0 * penetr
                     + 10.0 * contact + 10.0 * consist + (loss_h + loss_o);
        out[0] = (float)total;
#pragma unroll
        for (int q = 0; q < 8; q++) g_acc[q] = 0.0;
    }
}

extern "C" void kernel_launch(void* const* d_in, const int* in_sizes, int n_in,
                              void* d_out, int out_size) {
    const float* recon   = (const float*)d_in[0];
    const float* gt      = (const float*)d_in[1];
    const float* recon_n = (const float*)d_in[2];
    const float* gt_n    = (const float*)d_in[3];
    const float* obj     = (const float*)d_in[4];
    const float* mean    = (const float*)d_in[5];
    const float* logv    = (const float*)d_in[6];
    const float* vw      = (const float*)d_in[7];
    float* out = (float*)d_out;

    void* args[] = {
        (void*)&recon, (void*)&gt, (void*)&recon_n, (void*)&gt_n,
        (void*)&obj, (void*)&mean, (void*)&logv, (void*)&vw, (void*)&out
    };
    cudaLaunchCooperativeKernel((void*)k_all, dim3(GRID_BLOCKS), dim3(256), args, 0, 0);
}